// round 6
// baseline (speedup 1.0000x reference)
#include <cuda_runtime.h>
#include <cuda_bf16.h>

#define D 64
#define MAXN 100000
#define MAXE 1600000
#define ALPHA 0.2f
#define EPS 1e-10f

// ---------------- device scratch (static; no allocation allowed) ----------------
__device__ __align__(16) float g_vq[D];        // wq @ W (folded projection)
__device__ __align__(16) float g_vk[D];        // wk @ W
__device__ float g_cq;                          // wq . b
__device__ float g_ck;                          // wk . b + attend_b
__device__ int   g_is64;                        // edge_index dtype flag (sniffed)
__device__ __align__(16) float g_qs[MAXN];     // per-q-node scalar
__device__ __align__(16) float g_ks[MAXN];     // per-kv-node scalar
__device__ __align__(16) float g_kvproj[MAXN * D];  // kv_proj table (25.6MB, L2-resident)
__device__ __align__(16) float g_eexp[MAXE];   // exp(leaky(e)) per edge
__device__ __align__(16) int2  g_qk[MAXE];     // edge indices narrowed to int32
__device__ __align__(16) float g_esum[MAXN];   // softmax denominators

// ---------------- kernel 0: sniff edge_index dtype ----------------
// int64 non-negative indices -> every odd 32-bit word is a zero high-half.
// int32 indices in [0,100000) -> odd words are ordinary values (P(0) ~ 1e-5).
__global__ void sniff_kernel(const int* __restrict__ ei32) {
    if (threadIdx.x == 0) {
        int zeros = 0;
        for (int i = 1; i < 256; i += 2) zeros += (ei32[i] == 0);
        g_is64 = (zeros >= 120) ? 1 : 0;    // out of 128 odd slots
    }
}

// ---------------- kernel 1: fold attend_w through proj_w (tiny) ----------------
__global__ void prep_kernel(const float* __restrict__ W, const float* __restrict__ b,
                            const float* __restrict__ aw, const float* __restrict__ ab) {
    int t = threadIdx.x;
    if (t < D) {
        float s = 0.f;
        for (int d = 0; d < D; d++) s += aw[d] * W[d * D + t];
        g_vq[t] = s;
    } else {
        int k = t - D;
        float s = 0.f;
        for (int d = 0; d < D; d++) s += aw[D + d] * W[d * D + k];
        g_vk[k] = s;
    }
    if (t == 0) {
        float cq = 0.f, ck = 0.f;
        for (int d = 0; d < D; d++) { cq += b[d] * aw[d]; ck += b[d] * aw[D + d]; }
        g_cq = cq;
        g_ck = ck + ab[0];
    }
}

// ---------------- kernel 2: per-node attention scalars (warp per node) ----------------
__global__ void scalars_kernel(const float* __restrict__ q, const float* __restrict__ kv,
                               int Nq, int Nk) {
    int lane = threadIdx.x & 31;
    int warp = (blockIdx.x * blockDim.x + threadIdx.x) >> 5;
    int nwarps = (gridDim.x * blockDim.x) >> 5;
    float vq0 = g_vq[lane], vq1 = g_vq[lane + 32];
    float vk0 = g_vk[lane], vk1 = g_vk[lane + 32];
    float cq = g_cq, ck = g_ck;
    int Nmax = Nq > Nk ? Nq : Nk;
    for (int n = warp; n < Nmax; n += nwarps) {
        if (n < Nq) {
            float a = q[n * D + lane] * vq0 + q[n * D + lane + 32] * vq1;
            #pragma unroll
            for (int off = 16; off; off >>= 1) a += __shfl_xor_sync(0xffffffffu, a, off);
            if (lane == 0) g_qs[n] = a + cq;
        }
        if (n < Nk) {
            float a = kv[n * D + lane] * vk0 + kv[n * D + lane + 32] * vk1;
            #pragma unroll
            for (int off = 16; off; off >>= 1) a += __shfl_xor_sync(0xffffffffu, a, off);
            if (lane == 0) g_ks[n] = a + ck;
        }
    }
}

// ---------------- kernel 3: kv projection table (persistent blocks, smem W) ----------------
__global__ void kvproj_kernel(const float* __restrict__ kv, const float* __restrict__ W,
                              const float* __restrict__ b, int Nk) {
    __shared__ __align__(16) float Wp[D * 68];   // row-padded to 68 floats
    __shared__ __align__(16) float xs[2][68];
    int tid = threadIdx.x;           // 128
    for (int i = tid; i < D * D; i += 128) {
        int d = i >> 6, k = i & 63;
        Wp[d * 68 + k] = W[i];
    }
    int g = tid >> 6, d = tid & 63;
    float bd = b[d];
    __syncthreads();
    int pairs = (Nk + 1) >> 1;
    for (int p = blockIdx.x; p < pairs; p += gridDim.x) {
        int n = p * 2 + g;
        __syncthreads();                       // protect xs from previous iteration
        if (n < Nk) xs[g][d] = kv[n * D + d];
        __syncthreads();
        if (n < Nk) {
            float acc = bd;
            #pragma unroll
            for (int k = 0; k < D; k += 4) {
                float4 w4 = *(const float4*)&Wp[d * 68 + k];
                float4 x4 = *(const float4*)&xs[g][k];
                acc += w4.x * x4.x + w4.y * x4.y + w4.z * x4.z + w4.w * x4.w;
            }
            g_kvproj[n * D + d] = acc;
        }
    }
}

// ---------------- kernel 4: zero output + softmax denominators ----------------
__global__ void zero_kernel(float4* __restrict__ out4, int n4, int Nq) {
    int i = blockIdx.x * blockDim.x + threadIdx.x;
    int stride = gridDim.x * blockDim.x;
    for (int j = i; j < n4; j += stride) out4[j] = make_float4(0.f, 0.f, 0.f, 0.f);
    for (int j = i; j < Nq; j += stride) g_esum[j] = 0.f;
}

// ---------------- kernel 5: edge pass 1 — exp weights + denominator atomics ----------------
__global__ void edge1_kernel(const int* __restrict__ ei32, int E, int Nq, int Nk) {
    int e = blockIdx.x * blockDim.x + threadIdx.x;
    if (e >= E) return;
    int qi, ki;
    if (g_is64) {
        const long long* ei = (const long long*)ei32;
        qi = (int)ei[e];
        ki = (int)ei[E + e];
    } else {
        qi = ei32[e];
        ki = ei32[E + e];
    }
    // trap-proof clamp (indices are valid per reference; cost is noise)
    qi = min(max(qi, 0), Nq - 1);
    ki = min(max(ki, 0), Nk - 1);
    float s = g_qs[qi] + g_ks[ki];
    s = s > 0.f ? s : ALPHA * s;          // leaky relu
    float w = __expf(s);                   // no max-subtraction needed: |s| <= ~6
    g_eexp[e] = w;
    g_qk[e] = make_int2(qi, ki);
    atomicAdd(&g_esum[qi], w);
}

// ---------------- kernel 6: edge pass 2 — weighted scatter-add (16 lanes/edge) ----------------
__global__ void edge2_kernel(float4* __restrict__ out4, int E) {
    int gt = blockIdx.x * blockDim.x + threadIdx.x;
    int e = gt >> 4;
    if (e >= E) return;
    int sub = gt & 15;
    int2 qk = g_qk[e];
    float a = g_eexp[e] / (g_esum[qk.x] + EPS);
    float4 v = ((const float4*)g_kvproj)[qk.y * 16 + sub];
    float4 r = make_float4(v.x * a, v.y * a, v.z * a, v.w * a);
    atomicAdd(&out4[qk.x * 16 + sub], r);   // vector f32 atomics: sm_90+
}

// ---------------- launch ----------------
extern "C" void kernel_launch(void* const* d_in, const int* in_sizes, int n_in,
                              void* d_out, int out_size) {
    // Positional mapping per metadata order (= reference dict order):
    //   0: query_nodes (Nq*64 f32)   1: key_value_nodes (Nk*64 f32)
    //   2: edge_index (2*E, int32 OR int64 — sniffed at runtime)
    //   3: proj_w (4096)  4: proj_b (64)  5: attend_w (128)  6: attend_b (1)
    const float* q    = (const float*)d_in[0];
    const float* kv   = (const float*)d_in[1];
    const int*   ei32 = (const int*)d_in[2];
    const float* W    = (const float*)d_in[3];
    const float* b    = (const float*)d_in[4];
    const float* aw   = (const float*)d_in[5];
    const float* ab   = (const float*)d_in[6];
    int Nq = in_sizes[0] / D;
    int Nk = in_sizes[1] / D;
    int E  = in_sizes[2] / 2;     // element count is dtype-independent: 2*E
    float* out = (float*)d_out;

    sniff_kernel<<<1, 32>>>(ei32);

    prep_kernel<<<1, 128>>>(W, b, aw, ab);

    int Nmax = Nq > Nk ? Nq : Nk;
    int sc_blocks = (Nmax * 32 + 255) / 256;
    if (sc_blocks > 16384) sc_blocks = 16384;
    scalars_kernel<<<sc_blocks, 256>>>(q, kv, Nq, Nk);

    kvproj_kernel<<<1184, 128>>>(kv, W, b, Nk);

    zero_kernel<<<2048, 256>>>((float4*)out, out_size / 4, Nq);

    edge1_kernel<<<(E + 255) / 256, 256>>>(ei32, E, Nq, Nk);

    long long lanes = (long long)E * 16;
    int e2_blocks = (int)((lanes + 255) / 256);
    edge2_kernel<<<e2_blocks, 256>>>((float4*)out, E);
}

// round 9
// speedup vs baseline: 1.2206x; 1.2206x over previous
#include <cuda_runtime.h>
#include <cuda_bf16.h>

#define D 64
#define MAXN 100000
#define MAXE 1600000
#define ALPHA 0.2f
#define EPS 1e-10f

// ---------------- device scratch ----------------
__device__ __align__(16) float g_vq[D];
__device__ __align__(16) float g_vk[D];
__device__ float g_cq;
__device__ float g_ck;
__device__ int   g_is64;
__device__ __align__(16) float g_qs[MAXN];
__device__ __align__(16) float g_ks[MAXN];
__device__ __align__(16) float g_kvproj[MAXN * D];   // 25.6MB, L2-resident
__device__ __align__(16) float g_esum[MAXN];

// ---------------- kernel 0: sniff edge_index dtype ----------------
__global__ void sniff_kernel(const int* __restrict__ ei32) {
    if (threadIdx.x == 0) {
        int zeros = 0;
        for (int i = 1; i < 256; i += 2) zeros += (ei32[i] == 0);
        g_is64 = (zeros >= 120) ? 1 : 0;
    }
}

// ---------------- kernel 1: fold attend_w through proj_w ----------------
__global__ void prep_kernel(const float* __restrict__ W, const float* __restrict__ b,
                            const float* __restrict__ aw, const float* __restrict__ ab) {
    int t = threadIdx.x;
    if (t < D) {
        float s = 0.f;
        for (int d = 0; d < D; d++) s += aw[d] * W[d * D + t];
        g_vq[t] = s;
    } else {
        int k = t - D;
        float s = 0.f;
        for (int d = 0; d < D; d++) s += aw[D + d] * W[d * D + k];
        g_vk[k] = s;
    }
    if (t == 0) {
        float cq = 0.f, ck = 0.f;
        for (int d = 0; d < D; d++) { cq += b[d] * aw[d]; ck += b[d] * aw[D + d]; }
        g_cq = cq;
        g_ck = ck + ab[0];
    }
}

// ---------------- kernel 2: per-node attention scalars ----------------
__global__ void scalars_kernel(const float* __restrict__ q, const float* __restrict__ kv,
                               int Nq, int Nk) {
    int lane = threadIdx.x & 31;
    int warp = (blockIdx.x * blockDim.x + threadIdx.x) >> 5;
    int nwarps = (gridDim.x * blockDim.x) >> 5;
    float vq0 = g_vq[lane], vq1 = g_vq[lane + 32];
    float vk0 = g_vk[lane], vk1 = g_vk[lane + 32];
    float cq = g_cq, ck = g_ck;
    int Nmax = Nq > Nk ? Nq : Nk;
    for (int n = warp; n < Nmax; n += nwarps) {
        if (n < Nq) {
            float a = q[n * D + lane] * vq0 + q[n * D + lane + 32] * vq1;
            #pragma unroll
            for (int off = 16; off; off >>= 1) a += __shfl_xor_sync(0xffffffffu, a, off);
            if (lane == 0) g_qs[n] = a + cq;
        }
        if (n < Nk) {
            float a = kv[n * D + lane] * vk0 + kv[n * D + lane + 32] * vk1;
            #pragma unroll
            for (int off = 16; off; off >>= 1) a += __shfl_xor_sync(0xffffffffu, a, off);
            if (lane == 0) g_ks[n] = a + ck;
        }
    }
}

// ---------------- kernel 3: kv projection — register-blocked tiled GEMM ----------------
// 64-node tile, 256 threads, 4x4 micro-tile per thread.
// Thread (tx=tid&15, ty=tid>>4) computes nodes n=ty+16i, dims d=tx+16j.
// Row pad 76 floats (304B, 16B-aligned; float4-stride 19 = odd -> even bank-phase spread).
#define KV_PAD 76
__global__ void kvproj_kernel(const float* __restrict__ kv, const float* __restrict__ W,
                              const float* __restrict__ b, int Nk) {
    __shared__ __align__(16) float Wp[D * KV_PAD];
    __shared__ __align__(16) float Xs[D * KV_PAD];
    int tid = threadIdx.x;
    int tx = tid & 15, ty = tid >> 4;

    // load W (row d, inner k) once per block
    for (int i = tid; i < D * 16; i += 256) {
        int d = i >> 4, kq = i & 15;
        float4 w4 = ((const float4*)W)[i];
        *(float4*)&Wp[d * KV_PAD + kq * 4] = w4;
    }
    float bd[4];
    #pragma unroll
    for (int j = 0; j < 4; j++) bd[j] = b[tx + 16 * j];

    int ntiles = (Nk + 63) >> 6;
    for (int tile = blockIdx.x; tile < ntiles; tile += gridDim.x) {
        int base = tile << 6;
        __syncthreads();   // previous Xs fully consumed
        for (int i = tid; i < D * 16; i += 256) {
            int n = i >> 4, kq = i & 15;
            int gn = base + n;
            float4 v = (gn < Nk) ? ((const float4*)kv)[gn * 16 + kq]
                                 : make_float4(0.f, 0.f, 0.f, 0.f);
            *(float4*)&Xs[n * KV_PAD + kq * 4] = v;
        }
        __syncthreads();

        float acc[4][4];
        #pragma unroll
        for (int i = 0; i < 4; i++)
            #pragma unroll
            for (int j = 0; j < 4; j++) acc[i][j] = 0.f;

        #pragma unroll
        for (int k = 0; k < D; k += 4) {
            float4 xv[4], wv[4];
            #pragma unroll
            for (int i = 0; i < 4; i++) xv[i] = *(const float4*)&Xs[(ty + 16 * i) * KV_PAD + k];
            #pragma unroll
            for (int j = 0; j < 4; j++) wv[j] = *(const float4*)&Wp[(tx + 16 * j) * KV_PAD + k];
            #pragma unroll
            for (int i = 0; i < 4; i++)
                #pragma unroll
                for (int j = 0; j < 4; j++) {
                    acc[i][j] += xv[i].x * wv[j].x;
                    acc[i][j] += xv[i].y * wv[j].y;
                    acc[i][j] += xv[i].z * wv[j].z;
                    acc[i][j] += xv[i].w * wv[j].w;
                }
        }

        #pragma unroll
        for (int i = 0; i < 4; i++) {
            int gn = base + ty + 16 * i;
            if (gn < Nk) {
                #pragma unroll
                for (int j = 0; j < 4; j++)
                    g_kvproj[gn * D + tx + 16 * j] = acc[i][j] + bd[j];
            }
        }
    }
}

// ---------------- kernel 4: zero output + denominators ----------------
__global__ void zero_kernel(float4* __restrict__ out4, int n4, int Nq) {
    int i = blockIdx.x * blockDim.x + threadIdx.x;
    int stride = gridDim.x * blockDim.x;
    for (int j = i; j < n4; j += stride) out4[j] = make_float4(0.f, 0.f, 0.f, 0.f);
    for (int j = i; j < Nq; j += stride) g_esum[j] = 0.f;
}

// ---------------- kernel 5: fused edge pass — exp + esum + weighted scatter ----------------
// Post-normalization identity: out = (sum_e w_e * v_e) / (sum_e w_e + EPS).
// 16 lanes per edge; redundant scalar math across lanes is free (one warp instr).
__global__ void edge_kernel(float4* __restrict__ out4, const int* __restrict__ ei32,
                            int E, int Nq, int Nk) {
    int gt = blockIdx.x * blockDim.x + threadIdx.x;
    int e = gt >> 4;
    if (e >= E) return;
    int sub = gt & 15;
    int qi, ki;
    if (g_is64) {
        const long long* ei = (const long long*)ei32;
        qi = (int)ei[e];
        ki = (int)ei[E + e];
    } else {
        qi = ei32[e];
        ki = ei32[E + e];
    }
    qi = min(max(qi, 0), Nq - 1);
    ki = min(max(ki, 0), Nk - 1);
    float s = g_qs[qi] + g_ks[ki];
    s = s > 0.f ? s : ALPHA * s;
    float w = __expf(s);
    if (sub == 0) atomicAdd(&g_esum[qi], w);
    float4 v = ((const float4*)g_kvproj)[ki * 16 + sub];
    atomicAdd(&out4[qi * 16 + sub], make_float4(v.x * w, v.y * w, v.z * w, v.w * w));
}

// ---------------- kernel 6: final normalization ----------------
__global__ void norm_kernel(float4* __restrict__ out4, int Nq) {
    int i = blockIdx.x * blockDim.x + threadIdx.x;
    if (i >= Nq * 16) return;
    float inv = 1.f / (g_esum[i >> 4] + EPS);
    float4 v = out4[i];
    out4[i] = make_float4(v.x * inv, v.y * inv, v.z * inv, v.w * inv);
}

// ---------------- launch ----------------
extern "C" void kernel_launch(void* const* d_in, const int* in_sizes, int n_in,
                              void* d_out, int out_size) {
    const float* q    = (const float*)d_in[0];
    const float* kv   = (const float*)d_in[1];
    const int*   ei32 = (const int*)d_in[2];
    const float* W    = (const float*)d_in[3];
    const float* b    = (const float*)d_in[4];
    const float* aw   = (const float*)d_in[5];
    const float* ab   = (const float*)d_in[6];
    int Nq = in_sizes[0] / D;
    int Nk = in_sizes[1] / D;
    int E  = in_sizes[2] / 2;
    float* out = (float*)d_out;

    sniff_kernel<<<1, 32>>>(ei32);
    prep_kernel<<<1, 128>>>(W, b, aw, ab);

    int Nmax = Nq > Nk ? Nq : Nk;
    int sc_blocks = (Nmax * 32 + 255) / 256;
    if (sc_blocks > 16384) sc_blocks = 16384;
    scalars_kernel<<<sc_blocks, 256>>>(q, kv, Nq, Nk);

    kvproj_kernel<<<592, 256>>>(kv, W, b, Nk);

    zero_kernel<<<2048, 256>>>((float4*)out, out_size / 4, Nq);

    long long lanes = (long long)E * 16;
    int e_blocks = (int)((lanes + 255) / 256);
    edge_kernel<<<e_blocks, 256>>>((float4*)out, ei32, E, Nq, Nk);

    norm_kernel<<<(Nq * 16 + 255) / 256, 256>>>((float4*)out, Nq);
}